// round 17
// baseline (speedup 1.0000x reference)
#include <cuda_runtime.h>
#include <cstdint>

#define L_SEQ 4096
#define BATCH 256
#define NORD  64
#define TCH   32
#define CCH   128   // L_SEQ / TCH
#define BS3   64    // batch quarter per phase-3 CTA

typedef unsigned long long ull;

__device__ __forceinline__ ull bcast2(float a) {
    ull r; asm("mov.b64 %0, {%1, %1};" : "=l"(r) : "f"(a)); return r;
}
__device__ __forceinline__ void ffma2(ull &d, ull a, ull b) {
    asm("fma.rn.f32x2 %0, %1, %2, %0;" : "+l"(d) : "l"(a), "l"(b));
}
__device__ __forceinline__ float2 unpack2(ull v) {
    float2 f; asm("mov.b64 {%0, %1}, %2;" : "=f"(f.x), "=f"(f.y) : "l"(v)); return f;
}

// Scratch (static device globals: no allocations allowed)
__device__ float g_P[(size_t)CCH * NORD * NORD];   // [c][i][j]  row-major P_c   2 MB
__device__ float g_S[(size_t)CCH * BATCH * NORD];  // [c][b][i]  chunk sources   8 MB
__device__ float g_X[(size_t)CCH * BATCH * NORD];  // [c][b][i]  boundary states 8 MB

// ---------------------------------------------------------------------------
// Phase 1 (round-9 version, measured ~96us)
// ---------------------------------------------------------------------------
__global__ __launch_bounds__(256) void phase1_kernel(
    const float* __restrict__ A, const float* __restrict__ Bv,
    const float* __restrict__ inp)
{
    __shared__ float Pt[NORD * NORD];
    __shared__ float As[NORD * NORD];
    __shared__ float Bs[NORD];
    __shared__ float W[TCH][NORD];

    const int c = blockIdx.x, tid = threadIdx.x;
    const int t0 = c * TCH;
    const int ri = (tid & 15) * 4;   // i-tile
    const int cj = (tid >> 4) * 4;   // j-tile

    for (int idx = tid; idx < NORD * NORD; idx += 256)
        Pt[idx] = ((idx >> 6) == (idx & 63)) ? 1.f : 0.f;
    {
        const float4* A4 = (const float4*)(A + (size_t)(t0 + TCH - 1) * (NORD * NORD));
        float4* As4 = (float4*)As;
        #pragma unroll
        for (int q = 0; q < 4; q++) As4[tid + q * 256] = A4[tid + q * 256];
        if (tid < 16)
            ((float4*)Bs)[tid] = ((const float4*)(Bv + (size_t)(t0 + TCH - 1) * NORD))[tid];
    }
    __syncthreads();

    #pragma unroll 1
    for (int t = TCH - 1; t >= 0; --t) {
        float4 apf0, apf1, apf2, apf3, bpf;
        if (t > 0) {
            const float4* An = (const float4*)(A + (size_t)(t0 + t - 1) * (NORD * NORD));
            apf0 = An[tid]; apf1 = An[tid + 256]; apf2 = An[tid + 512]; apf3 = An[tid + 768];
            if (tid < 16) bpf = ((const float4*)(Bv + (size_t)(t0 + t - 1) * NORD))[tid];
        }

        float w0 = 0.f, w1 = 0.f, w2 = 0.f, w3 = 0.f;
        if (tid < NORD) {
            #pragma unroll
            for (int k4 = 0; k4 < 16; k4++) {
                w0 += Pt[(4 * k4 + 0) * NORD + tid] * Bs[4 * k4 + 0];
                w1 += Pt[(4 * k4 + 1) * NORD + tid] * Bs[4 * k4 + 1];
                w2 += Pt[(4 * k4 + 2) * NORD + tid] * Bs[4 * k4 + 2];
                w3 += Pt[(4 * k4 + 3) * NORD + tid] * Bs[4 * k4 + 3];
            }
        }

        ull acc2[4][2];
        #pragma unroll
        for (int jj = 0; jj < 4; jj++) { acc2[jj][0] = 0ull; acc2[jj][1] = 0ull; }

        #pragma unroll 8
        for (int k = 0; k < NORD; k++) {
            ulonglong2 p = *(const ulonglong2*)&Pt[k * NORD + ri];
            float4 a = *(const float4*)&As[k * NORD + cj];
            ull b0 = bcast2(a.x), b1 = bcast2(a.y), b2 = bcast2(a.z), b3 = bcast2(a.w);
            ffma2(acc2[0][0], b0, p.x); ffma2(acc2[0][1], b0, p.y);
            ffma2(acc2[1][0], b1, p.x); ffma2(acc2[1][1], b1, p.y);
            ffma2(acc2[2][0], b2, p.x); ffma2(acc2[2][1], b2, p.y);
            ffma2(acc2[3][0], b3, p.x); ffma2(acc2[3][1], b3, p.y);
        }
        __syncthreads();

        if (tid < NORD) W[t][tid] = (w0 + w1) + (w2 + w3);
        if (t > 0) {
            #pragma unroll
            for (int jj = 0; jj < 4; jj++)
                *(ulonglong2*)&Pt[(cj + jj) * NORD + ri] =
                    make_ulonglong2(acc2[jj][0], acc2[jj][1]);
            float4* As4 = (float4*)As;
            As4[tid] = apf0; As4[tid + 256] = apf1; As4[tid + 512] = apf2; As4[tid + 768] = apf3;
            if (tid < 16) ((float4*)Bs)[tid] = bpf;
        } else {
            float f[4][4];
            #pragma unroll
            for (int jj = 0; jj < 4; jj++) {
                float2 v0 = unpack2(acc2[jj][0]); f[jj][0] = v0.x; f[jj][1] = v0.y;
                float2 v1 = unpack2(acc2[jj][1]); f[jj][2] = v1.x; f[jj][3] = v1.y;
            }
            float* gp = g_P + (size_t)c * (NORD * NORD);
            #pragma unroll
            for (int ii = 0; ii < 4; ii++)
                *(float4*)&gp[(ri + ii) * NORD + cj] =
                    make_float4(f[0][ii], f[1][ii], f[2][ii], f[3][ii]);
        }
        __syncthreads();
    }

    {
        float u[TCH];
        #pragma unroll
        for (int tt = 0; tt < TCH; tt++) u[tt] = inp[(size_t)(t0 + tt) * BATCH + tid];
        float* sp = g_S + ((size_t)c * BATCH + tid) * NORD;
        #pragma unroll
        for (int half = 0; half < 2; half++) {
            ull acc[16];
            #pragma unroll
            for (int m = 0; m < 16; m++) acc[m] = 0ull;
            #pragma unroll 4
            for (int tt = 0; tt < TCH; tt++) {
                ull ub = bcast2(u[tt]);
                const ull* wrow = (const ull*)&W[tt][half * 32];
                #pragma unroll
                for (int m = 0; m < 16; m++) ffma2(acc[m], ub, wrow[m]);
            }
            #pragma unroll
            for (int m2 = 0; m2 < 8; m2++)
                *(ulonglong2*)&sp[half * 32 + m2 * 4] =
                    make_ulonglong2(acc[2 * m2], acc[2 * m2 + 1]);
        }
    }
}

// ---------------------------------------------------------------------------
// Phase 2 (unchanged): X_c = P_c @ X_{c-1} + S_c
// ---------------------------------------------------------------------------
#define P2PAD 68
__global__ __launch_bounds__(256) void phase2_kernel()
{
    __shared__ float Ps[2][NORD * P2PAD];
    __shared__ float xsm[2][4][NORD];

    const int tid = threadIdx.x;
    const int b0 = blockIdx.x * 4;
    const int i  = tid >> 2;
    const int bb = tid & 3;

    {
        const float4* gp = (const float4*)g_P;
        #pragma unroll
        for (int q = 0; q < 4; q++) {
            int f = tid + q * 256;
            int ii = f >> 4, j4 = f & 15;
            *(float4*)&Ps[0][ii * P2PAD + j4 * 4] = gp[f];
        }
        xsm[0][bb][i] = 0.f;
    }
    float s_cur = g_S[((size_t)b0 + bb) * NORD + i];
    __syncthreads();

    int cur = 0;
    #pragma unroll 1
    for (int c = 0; c < CCH; c++) {
        float4 pf0, pf1, pf2, pf3; float s_nxt = 0.f;
        if (c + 1 < CCH) {
            const float4* gp = (const float4*)(g_P + (size_t)(c + 1) * (NORD * NORD));
            pf0 = gp[tid]; pf1 = gp[tid + 256]; pf2 = gp[tid + 512]; pf3 = gp[tid + 768];
            s_nxt = g_S[((size_t)(c + 1) * BATCH + b0 + bb) * NORD + i];
        }

        ull a0 = 0ull, a1 = 0ull, a2 = 0ull, a3 = 0ull;
        const float* prow = &Ps[cur][i * P2PAD];
        const float* xrow = &xsm[cur][bb][0];
        #pragma unroll
        for (int j8 = 0; j8 < 8; j8++) {
            ulonglong2 p0 = *(const ulonglong2*)(prow + j8 * 8);
            ulonglong2 p1 = *(const ulonglong2*)(prow + j8 * 8 + 4);
            ulonglong2 x0 = *(const ulonglong2*)(xrow + j8 * 8);
            ulonglong2 x1 = *(const ulonglong2*)(xrow + j8 * 8 + 4);
            ffma2(a0, p0.x, x0.x); ffma2(a1, p0.y, x0.y);
            ffma2(a2, p1.x, x1.x); ffma2(a3, p1.y, x1.y);
        }
        float2 f0 = unpack2(a0), f1 = unpack2(a1), f2 = unpack2(a2), f3 = unpack2(a3);
        float acc = s_cur + ((f0.x + f0.y) + (f1.x + f1.y)) + ((f2.x + f2.y) + (f3.x + f3.y));

        const int nxt = cur ^ 1;
        xsm[nxt][bb][i] = acc;
        g_X[((size_t)c * BATCH + b0 + bb) * NORD + i] = acc;
        if (c + 1 < CCH) {
            #pragma unroll
            for (int q = 0; q < 4; q++) {
                float4 pv = (q == 0) ? pf0 : (q == 1) ? pf1 : (q == 2) ? pf2 : pf3;
                int f = tid + q * 256;
                int ii = f >> 4, j4 = f & 15;
                *(float4*)&Ps[nxt][ii * P2PAD + j4 * 4] = pv;
            }
        }
        s_cur = s_nxt;
        __syncthreads();
        cur = nxt;
    }
}

// ---------------------------------------------------------------------------
// Phase 3 (PAIRED): one CTA processes TWO independent chunks (c0 = 2p,
// c1 = 2p+1, both inits known from g_X) with a FUSED k-loop: per k it loads
// X and A for BOTH chunks and feeds both accumulator sets.  Barriers per
// unit work HALVE; independent work between barriers DOUBLES; numerics are
// identical to the single-chunk version.
// grid = 64 pairs x 4 batch quarters = 256 CTAs, 256 threads, 2 CTAs/SM.
// Thread (riq = tid>>5 warp-uniform, bq = 2*(tid&31)): rows {riq+8m},
// 2 batches.  A staged PERMUTED (As[k][(i&7)*8+(i>>3)]), single-buffered
// (barrier A ends reads, barrier B publishes restage).
// ---------------------------------------------------------------------------
#define P3_APAD 68

__device__ __forceinline__ void p3_stage_AB(float* As, float* Bs,
                                            const float4* apf, float4 bpf, int tid) {
    #pragma unroll
    for (int q = 0; q < 4; q++) {
        int f = tid + q * 256;              // float4 idx: i = f>>4, j = 4*(f&15)
        int i = f >> 4, j0 = (f & 15) * 4;
        int p = ((i & 7) << 3) | (i >> 3);  // permuted row position
        float4 v = apf[q];
        As[(j0 + 0) * P3_APAD + p] = v.x;
        As[(j0 + 1) * P3_APAD + p] = v.y;
        As[(j0 + 2) * P3_APAD + p] = v.z;
        As[(j0 + 3) * P3_APAD + p] = v.w;
    }
    if (tid < 16) {
        #pragma unroll
        for (int r = 0; r < 4; r++) {
            int i = 4 * tid + r;
            float v = (r == 0) ? bpf.x : (r == 1) ? bpf.y : (r == 2) ? bpf.z : bpf.w;
            Bs[((i & 7) << 3) | (i >> 3)] = v;
        }
    }
}

__global__ __launch_bounds__(256, 2) void phase3_kernel(
    const float* __restrict__ A, const float* __restrict__ Bv,
    const float* __restrict__ inp, float* __restrict__ out)
{
    __shared__ float As0[NORD * P3_APAD];
    __shared__ float As1[NORD * P3_APAD];
    __shared__ float xs0[NORD * BS3];
    __shared__ float xs1[NORD * BS3];
    __shared__ float Bs0[NORD];
    __shared__ float Bs1[NORD];

    const int tid = threadIdx.x;
    const int pair = blockIdx.x >> 2;
    const int b0   = (blockIdx.x & 3) * BS3;
    const int c0   = 2 * pair, c1 = 2 * pair + 1;
    const int t0_0 = c0 * TCH, t0_1 = c1 * TCH;
    const int riq = tid >> 5;              // warp-uniform row offset 0..7
    const int bq  = (tid & 31) * 2;        // 2 batches per thread

    // stage A,B for t=0 of both chunks
    {
        const float4* A40 = (const float4*)(A + (size_t)t0_0 * (NORD * NORD));
        const float4* A41 = (const float4*)(A + (size_t)t0_1 * (NORD * NORD));
        float4 apf0[4], apf1[4];
        #pragma unroll
        for (int q = 0; q < 4; q++) { apf0[q] = A40[tid + q * 256]; apf1[q] = A41[tid + q * 256]; }
        float4 bpf0 = make_float4(0.f,0.f,0.f,0.f), bpf1 = bpf0;
        if (tid < 16) {
            bpf0 = ((const float4*)(Bv + (size_t)t0_0 * NORD))[tid];
            bpf1 = ((const float4*)(Bv + (size_t)t0_1 * NORD))[tid];
        }
        p3_stage_AB(As0, Bs0, apf0, bpf0, tid);
        p3_stage_AB(As1, Bs1, apf1, bpf1, tid);
    }
    ull ucur0 = *(const ull*)(inp + (size_t)t0_0 * BATCH + b0 + bq);
    ull ucur1 = *(const ull*)(inp + (size_t)t0_1 * BATCH + b0 + bq);

    // load initial states: thread = (bcol = tid&63, jq = tid>>6), 16 j's each
    {
        const int bcol = tid & 63, jq = tid >> 6;
        if (c0 == 0) {
            #pragma unroll
            for (int j = 0; j < 16; j++) xs0[(jq * 16 + j) * BS3 + bcol] = 0.f;
        } else {
            const float4* Xp = (const float4*)(g_X + (((size_t)(c0 - 1)) * BATCH + b0 + bcol) * NORD + jq * 16);
            #pragma unroll
            for (int j4 = 0; j4 < 4; j4++) {
                float4 v = Xp[j4];
                xs0[(jq * 16 + 4 * j4 + 0) * BS3 + bcol] = v.x;
                xs0[(jq * 16 + 4 * j4 + 1) * BS3 + bcol] = v.y;
                xs0[(jq * 16 + 4 * j4 + 2) * BS3 + bcol] = v.z;
                xs0[(jq * 16 + 4 * j4 + 3) * BS3 + bcol] = v.w;
            }
        }
        {
            const float4* Xp = (const float4*)(g_X + (((size_t)(c1 - 1)) * BATCH + b0 + bcol) * NORD + jq * 16);
            #pragma unroll
            for (int j4 = 0; j4 < 4; j4++) {
                float4 v = Xp[j4];
                xs1[(jq * 16 + 4 * j4 + 0) * BS3 + bcol] = v.x;
                xs1[(jq * 16 + 4 * j4 + 1) * BS3 + bcol] = v.y;
                xs1[(jq * 16 + 4 * j4 + 2) * BS3 + bcol] = v.z;
                xs1[(jq * 16 + 4 * j4 + 3) * BS3 + bcol] = v.w;
            }
        }
    }
    __syncthreads();

    #pragma unroll 1
    for (int t = 0; t < TCH; t++) {
        // prefetch next A,B,u for both chunks
        float4 apf0[4], apf1[4]; float4 bpf0, bpf1; ull unxt0, unxt1;
        if (t < TCH - 1) {
            const float4* An0 = (const float4*)(A + (size_t)(t0_0 + t + 1) * (NORD * NORD));
            const float4* An1 = (const float4*)(A + (size_t)(t0_1 + t + 1) * (NORD * NORD));
            #pragma unroll
            for (int q = 0; q < 4; q++) { apf0[q] = An0[tid + q * 256]; apf1[q] = An1[tid + q * 256]; }
            if (tid < 16) {
                bpf0 = ((const float4*)(Bv + (size_t)(t0_0 + t + 1) * NORD))[tid];
                bpf1 = ((const float4*)(Bv + (size_t)(t0_1 + t + 1) * NORD))[tid];
            }
            unxt0 = *(const ull*)(inp + (size_t)(t0_0 + t + 1) * BATCH + b0 + bq);
            unxt1 = *(const ull*)(inp + (size_t)(t0_1 + t + 1) * BATCH + b0 + bq);
        }

        // init acc[m] = B[row]*u for both chunks
        ull acc0[8], acc1[8];
        {
            float4 B00 = *(const float4*)&Bs0[riq * 8];
            float4 B01 = *(const float4*)&Bs0[riq * 8 + 4];
            float4 B10 = *(const float4*)&Bs1[riq * 8];
            float4 B11 = *(const float4*)&Bs1[riq * 8 + 4];
            float b0a[8] = {B00.x, B00.y, B00.z, B00.w, B01.x, B01.y, B01.z, B01.w};
            float b1a[8] = {B10.x, B10.y, B10.z, B10.w, B11.x, B11.y, B11.z, B11.w};
            #pragma unroll
            for (int m = 0; m < 8; m++) {
                acc0[m] = 0ull; acc1[m] = 0ull;
                ffma2(acc0[m], bcast2(b0a[m]), ucur0);
                ffma2(acc1[m], bcast2(b1a[m]), ucur1);
            }
        }

        // fused triangular MACs for BOTH chunks: row riq+8m active for k<=riq+8m
        #define P3_ACCK(K, MSTART)                                              \
        {                                                                       \
            ull X0 = *(const ull*)&xs0[(K) * BS3 + bq];                         \
            ull X1 = *(const ull*)&xs1[(K) * BS3 + bq];                         \
            float a0[8], a1[8];                                                 \
            if ((MSTART) < 4) {                                                 \
                float4 v0 = *(const float4*)&As0[(K) * P3_APAD + riq * 8];      \
                float4 v1 = *(const float4*)&As1[(K) * P3_APAD + riq * 8];      \
                a0[0]=v0.x; a0[1]=v0.y; a0[2]=v0.z; a0[3]=v0.w;                 \
                a1[0]=v1.x; a1[1]=v1.y; a1[2]=v1.z; a1[3]=v1.w;                 \
            }                                                                   \
            {                                                                   \
                float4 v0 = *(const float4*)&As0[(K) * P3_APAD + riq * 8 + 4];  \
                float4 v1 = *(const float4*)&As1[(K) * P3_APAD + riq * 8 + 4];  \
                a0[4]=v0.x; a0[5]=v0.y; a0[6]=v0.z; a0[7]=v0.w;                 \
                a1[4]=v1.x; a1[5]=v1.y; a1[6]=v1.z; a1[7]=v1.w;                 \
            }                                                                   \
            _Pragma("unroll")                                                   \
            for (int m = (MSTART); m < 8; m++) {                                \
                ffma2(acc0[m], bcast2(a0[m]), X0);                              \
                ffma2(acc1[m], bcast2(a1[m]), X1);                              \
            }                                                                   \
        }

        // block 0: k = 0..riq (warp-uniform trip), all rows
        #pragma unroll 1
        for (int k = 0; k <= riq; k++) P3_ACCK(k, 0);

        // KBLOCK(MB): 8 k's in [riq+8(MB-1)+1, riq+8MB], rows m >= MB
        #define P3_KBLOCK(MB)                                                   \
        {                                                                       \
            const int kbase = riq + 8 * ((MB) - 1) + 1;                         \
            _Pragma("unroll 4")                                                 \
            for (int kk = 0; kk < 8; kk++) P3_ACCK(kbase + kk, MB);             \
        }
        P3_KBLOCK(1) P3_KBLOCK(2) P3_KBLOCK(3) P3_KBLOCK(4)
        P3_KBLOCK(5) P3_KBLOCK(6) P3_KBLOCK(7)
        #undef P3_KBLOCK
        #undef P3_ACCK

        __syncthreads();   // (A) everyone done reading xs AND As/Bs

        // store new states (8B lane stride -> conflict-free)
        #pragma unroll
        for (int m = 0; m < 8; m++) {
            *(ull*)&xs0[(riq + 8 * m) * BS3 + bq] = acc0[m];
            *(ull*)&xs1[(riq + 8 * m) * BS3 + bq] = acc1[m];
        }
        // restage A,B into the SAME buffers (reads finished at barrier A)
        if (t < TCH - 1) {
            p3_stage_AB(As0, Bs0, apf0, bpf0, tid);
            p3_stage_AB(As1, Bs1, apf1, bpf1, tid);
        }
        __syncthreads();   // (B) states + restaged A visible

        // copy out x_t for both chunks: thread = (bcol = tid&63, iq = tid>>6)
        {
            const int bcol = tid & 63, iq = tid >> 6;
            float* op0 = out + ((size_t)(t0_0 + t) * BATCH + b0 + bcol) * NORD + iq * 16;
            float* op1 = out + ((size_t)(t0_1 + t) * BATCH + b0 + bcol) * NORD + iq * 16;
            const float* col0 = xs0 + bcol;
            const float* col1 = xs1 + bcol;
            #pragma unroll
            for (int i4 = 0; i4 < 4; i4++) {
                float4 v0 = make_float4(col0[(iq * 16 + 4 * i4 + 0) * BS3],
                                        col0[(iq * 16 + 4 * i4 + 1) * BS3],
                                        col0[(iq * 16 + 4 * i4 + 2) * BS3],
                                        col0[(iq * 16 + 4 * i4 + 3) * BS3]);
                *(float4*)(op0 + 4 * i4) = v0;
                float4 v1 = make_float4(col1[(iq * 16 + 4 * i4 + 0) * BS3],
                                        col1[(iq * 16 + 4 * i4 + 1) * BS3],
                                        col1[(iq * 16 + 4 * i4 + 2) * BS3],
                                        col1[(iq * 16 + 4 * i4 + 3) * BS3]);
                *(float4*)(op1 + 4 * i4) = v1;
            }
        }
        ucur0 = unxt0; ucur1 = unxt1;
    }
}

// ---------------------------------------------------------------------------
extern "C" void kernel_launch(void* const* d_in, const int* in_sizes, int n_in,
                              void* d_out, int out_size)
{
    const float* inp = (const float*)d_in[0];   // (L, BATCH)
    const float* A   = (const float*)d_in[1];   // (L, N, N)
    const float* Bv  = (const float*)d_in[2];   // (L, N)
    float* out = (float*)d_out;                 // (L, BATCH, N)

    phase1_kernel<<<CCH, 256>>>(A, Bv, inp);
    phase2_kernel<<<BATCH / 4, 256>>>();
    phase3_kernel<<<(CCH / 2) * 4, 256>>>(A, Bv, inp, out);
}